// round 3
// baseline (speedup 1.0000x reference)
#include <cuda_runtime.h>
#include <cstdint>
#include <cstddef>

#define NROWS 8192
#define FD 64
#define CJ 128
#define TILE_I 64
#define JSPLIT 8
#define NWARP 8
#define RW 8

typedef unsigned long long ull;

// scratch (static __device__ globals: allocation-free per harness rules)
__device__ float g_Wh[NROWS * FD];              // 2 MB
__device__ float g_s[NROWS];
__device__ float g_d[NROWS];
__device__ float g_es[NROWS];                   // exp(s)
__device__ float g_fs[NROWS];                   // exp(0.2 s)
__device__ float g_ed[NROWS];                   // exp(d)
__device__ float g_fd[NROWS];                   // exp(0.2 d)
__device__ float g_pacc[JSPLIT][NROWS][FD];     // 16.8 MB partial O
__device__ float g_pl[JSPLIT][NROWS];           // partial row sums

// exp(t) on the FMA pipe. Magic-number round + degree-6 Taylor, rel err ~1e-7.
__device__ __forceinline__ float fast_exp(float t) {
    float x = t * 1.4426950408889634f;           // log2(e)
    x = fminf(fmaxf(x, -126.0f), 126.0f);
    float c = x + 12582912.0f;                   // 1.5*2^23
    int   ic = __float_as_int(c);
    float xi = c - 12582912.0f;
    float f  = x - xi;
    float y  = f * 0.6931471805599453f;
    float p = 1.3888889e-3f;
    p = fmaf(p, y, 8.3333333e-3f);
    p = fmaf(p, y, 4.1666667e-2f);
    p = fmaf(p, y, 1.6666667e-1f);
    p = fmaf(p, y, 0.5f);
    p = fmaf(p, y, 1.0f);
    p = fmaf(p, y, 1.0f);
    float sc = __int_as_float(((ic & 0x7FFFFF) - 0x400000 + 127) << 23);
    return p * sc;
}

// acc (f32x2 pair) += p_pair * wh_pair   (packed dual-fp32 FMA)
#define FFMA2(accv, pv, whv)                                                   \
    asm("fma.rn.f32x2 %0, %1, %2, %0;" : "+l"(accv) : "l"(pv), "l"(whv))

// ---------------------------------------------------------------------------
// Kernel 1: Wh = X@W, fused s/d = Wh@a_src / Wh@a_dst, fused exp factor tables.
// 16 rows per block, 128 threads: thread (r, fg) computes 8 features. grid=512.
// ---------------------------------------------------------------------------
__global__ __launch_bounds__(128) void k_wh(const float* __restrict__ inp,
                                            const float* __restrict__ W,
                                            const float* __restrict__ a) {
    __shared__ float sIn[16 * 65];
    __shared__ float sW[64 * 64];
    __shared__ float sA[128];
    int tid = threadIdx.x;
    int i0  = blockIdx.x * 16;
    for (int idx = tid; idx < 1024; idx += 128) {
        int r = idx >> 6, k = idx & 63;
        sIn[r * 65 + k] = inp[i0 * 64 + idx];
    }
    const float4* W4 = (const float4*)W;
    float4* sW4w = (float4*)sW;
#pragma unroll
    for (int q = 0; q < 8; ++q) sW4w[tid + q * 128] = W4[tid + q * 128];
    if (tid < 128) sA[tid] = a[tid];
    __syncthreads();

    int r = tid >> 3, fg = tid & 7;
    float acc[8];
#pragma unroll
    for (int q = 0; q < 8; ++q) acc[q] = 0.f;
    const float4* sW4 = (const float4*)sW;
#pragma unroll 8
    for (int k = 0; k < 64; ++k) {
        float x = sIn[r * 65 + k];
        float4 w0 = sW4[k * 16 + fg * 2 + 0];
        float4 w1 = sW4[k * 16 + fg * 2 + 1];
        acc[0] = fmaf(x, w0.x, acc[0]);
        acc[1] = fmaf(x, w0.y, acc[1]);
        acc[2] = fmaf(x, w0.z, acc[2]);
        acc[3] = fmaf(x, w0.w, acc[3]);
        acc[4] = fmaf(x, w1.x, acc[4]);
        acc[5] = fmaf(x, w1.y, acc[5]);
        acc[6] = fmaf(x, w1.z, acc[6]);
        acc[7] = fmaf(x, w1.w, acc[7]);
    }
    int row = i0 + r;
    float ps = 0.f, pd = 0.f;
#pragma unroll
    for (int q = 0; q < 8; ++q) {
        ps = fmaf(acc[q], sA[fg * 8 + q], ps);
        pd = fmaf(acc[q], sA[64 + fg * 8 + q], pd);
    }
    float4* whp = (float4*)(g_Wh + row * 64 + fg * 8);
    whp[0] = make_float4(acc[0], acc[1], acc[2], acc[3]);
    whp[1] = make_float4(acc[4], acc[5], acc[6], acc[7]);
#pragma unroll
    for (int o = 1; o < 8; o <<= 1) {
        ps += __shfl_xor_sync(0xffffffffu, ps, o, 8);
        pd += __shfl_xor_sync(0xffffffffu, pd, o, 8);
    }
    if (fg == 0) {
        float sc = fminf(fmaxf(ps, -87.f), 80.f);
        float dc = fminf(fmaxf(pd, -87.f), 80.f);
        g_s[row]  = ps;
        g_d[row]  = pd;
        g_es[row] = fast_exp(sc);
        g_fs[row] = fast_exp(0.2f * sc);
        g_ed[row] = fast_exp(dc);
        g_fd[row] = fast_exp(0.2f * dc);
    }
}

// ---------------------------------------------------------------------------
// Kernel 2: fused mask + factorized-exp softmax weights + P@Wh (f32x2 packed).
// Grid = 128 i-tiles x 8 j-splits. 256 thr / 8 warps, 8 rows/warp, CJ=128.
// ---------------------------------------------------------------------------
#define SMEM_WH_BYTES (CJ * FD * 4)                        // 32768
#define SMEM_D_OFF    SMEM_WH_BYTES                        // 3*128 floats = 1536B
#define SMEM_P_OFF    (SMEM_WH_BYTES + 1536)               // 34304
#define SMEM_TOTAL    (SMEM_P_OFF + NWARP * CJ * RW * 4)   // 67072

__global__ __launch_bounds__(256, 3) void k_attn(const int* __restrict__ adj) {
    extern __shared__ char smem[];
    float* sWh = (float*)smem;
    float* sD  = (float*)(smem + SMEM_D_OFF);          // d
    float* sED = sD + CJ;                              // exp(d)
    float* sFD = sD + 2 * CJ;                          // exp(0.2 d)
    int tid  = threadIdx.x;
    int wid  = tid >> 5, lane = tid & 31;
    float* sPmy = (float*)(smem + SMEM_P_OFF) + wid * CJ * RW;

    int itile  = blockIdx.x & 127;
    int sp     = blockIdx.x >> 7;
    int i0     = itile * TILE_I;
    int jbase0 = sp * (NROWS / JSPLIT);
    int row0   = i0 + wid * RW;

    float s[8], Es[8], Fs[8];
#pragma unroll
    for (int r = 0; r < 8; ++r) {
        s[r]  = g_s[row0 + r];
        Es[r] = g_es[row0 + r];
        Fs[r] = g_fs[row0 + r];
    }
    ull acc[8];
#pragma unroll
    for (int r = 0; r < 8; ++r) acc[r] = 0ULL;
    float lpart[8];
#pragma unroll
    for (int r = 0; r < 8; ++r) lpart[r] = 0.f;

    for (int cc = 0; cc < (NROWS / JSPLIT) / CJ; ++cc) {   // 8 chunks
        int jb = jbase0 + cc * CJ;
        __syncthreads();
        {   // cooperative load of Wh chunk (32 KB) + d/ed/fd chunk
            const float4* src  = (const float4*)(g_Wh + (size_t)jb * FD);
            float4*       dst4 = (float4*)sWh;
#pragma unroll
            for (int q = 0; q < 8; ++q) dst4[tid + q * 256] = src[tid + q * 256];
            if (tid < CJ) {
                sD[tid]  = g_d[jb + tid];
                sFD[tid] = g_fd[jb + tid];
            } else if (tid < 2 * CJ) {
                sED[tid - CJ] = g_ed[jb + tid - CJ];
            }
        }
        __syncthreads();

        // ---- Phase A: w = adj ? ((s+d>0) ? Es*Ed : Fs*Fd) : 0 ----
        const int* adjp = adj + (size_t)row0 * NROWS + jb;
#pragma unroll
        for (int g = 0; g < 4; ++g) {
            int   jl  = g * 32 + lane;
            float dj  = sD[jl];
            float edj = sED[jl];
            float fdj = sFD[jl];
            float w8[8];
#pragma unroll
            for (int r = 0; r < 8; ++r) {
                int   av  = __ldg(adjp + (size_t)r * NROWS + jl);
                float t   = s[r] + dj;
                bool  pos = t > 0.f;
                float ea  = pos ? Es[r] : Fs[r];
                float eb  = pos ? edj : fdj;
                ea        = (av > 0) ? ea : 0.f;
                float w   = ea * eb;
                lpart[r] += w;
                w8[r] = w;
            }
            float4* pd4 = (float4*)(sPmy + jl * 8);
            pd4[0] = make_float4(w8[0], w8[1], w8[2], w8[3]);
            pd4[1] = make_float4(w8[4], w8[5], w8[6], w8[7]);
        }
        __syncwarp();

        // ---- Phase B: row-pair-packed f32x2 GEMM  acc += P * Wh ----
        // acc[h*4+p] holds rows (2p,2p+1), feature h*32+lane.
#pragma unroll 8
        for (int jl = 0; jl < CJ; ++jl) {
            ulonglong2 pA = *(const ulonglong2*)(sPmy + jl * 8);      // {w0,w1},{w2,w3}
            ulonglong2 pB = *(const ulonglong2*)(sPmy + jl * 8 + 4);  // {w4,w5},{w6,w7}
            float wh0 = sWh[jl * 64 + lane];
            float wh1 = sWh[jl * 64 + 32 + lane];
            ull whp0, whp1;
            asm("mov.b64 %0, {%1,%1};" : "=l"(whp0) : "f"(wh0));
            asm("mov.b64 %0, {%1,%1};" : "=l"(whp1) : "f"(wh1));
            FFMA2(acc[0], pA.x, whp0);
            FFMA2(acc[1], pA.y, whp0);
            FFMA2(acc[2], pB.x, whp0);
            FFMA2(acc[3], pB.y, whp0);
            FFMA2(acc[4], pA.x, whp1);
            FFMA2(acc[5], pA.y, whp1);
            FFMA2(acc[6], pB.x, whp1);
            FFMA2(acc[7], pB.y, whp1);
        }
    }

    // epilogue: write split-partials
#pragma unroll
    for (int r = 0; r < 8; ++r) {
        float lr = lpart[r];
#pragma unroll
        for (int o = 16; o > 0; o >>= 1) lr += __shfl_xor_sync(0xffffffffu, lr, o);
        if (lane == 0) g_pl[sp][row0 + r] = lr;
    }
#pragma unroll
    for (int p = 0; p < 4; ++p) {
        float lo0, hi0, lo1, hi1;
        asm("mov.b64 {%0, %1}, %2;" : "=f"(lo0), "=f"(hi0) : "l"(acc[p]));
        asm("mov.b64 {%0, %1}, %2;" : "=f"(lo1), "=f"(hi1) : "l"(acc[4 + p]));
        int ra = row0 + 2 * p, rb = ra + 1;
        g_pacc[sp][ra][lane]      = lo0;
        g_pacc[sp][ra][lane + 32] = lo1;
        g_pacc[sp][rb][lane]      = hi0;
        g_pacc[sp][rb][lane + 32] = hi1;
    }
}

// ---------------------------------------------------------------------------
// Kernel 3: combine j-split partials, normalize, ELU
// ---------------------------------------------------------------------------
__global__ __launch_bounds__(256) void k_final(float* __restrict__ out) {
    int idx = blockIdx.x * 256 + threadIdx.x;   // 262144 threads
    int i = idx >> 5, l = idx & 31;
    float a0 = 0.f, a1 = 0.f, ls = 0.f;
#pragma unroll
    for (int sp = 0; sp < JSPLIT; ++sp) {
        float2 p = *(const float2*)(&g_pacc[sp][i][2 * l]);
        a0 += p.x; a1 += p.y;
        ls += g_pl[sp][i];
    }
    float inv = 1.0f / ls;
    a0 *= inv; a1 *= inv;
    a0 = (a0 > 0.f) ? a0 : (fast_exp(a0) - 1.f);   // elu
    a1 = (a1 > 0.f) ? a1 : (fast_exp(a1) - 1.f);
    *(float2*)(out + i * 64 + 2 * l) = make_float2(a0, a1);
}

extern "C" void kernel_launch(void* const* d_in, const int* in_sizes, int n_in,
                              void* d_out, int out_size) {
    const float* inp = (const float*)d_in[0];
    const int*   adj = (const int*)d_in[1];
    const float* W   = (const float*)d_in[2];
    const float* a   = (const float*)d_in[3];
    float*       out = (float*)d_out;

    cudaFuncSetAttribute(k_attn, cudaFuncAttributeMaxDynamicSharedMemorySize,
                         SMEM_TOTAL);

    k_wh<<<NROWS / 16, 128>>>(inp, W, a);
    k_attn<<<JSPLIT * (NROWS / TILE_I), 256, SMEM_TOTAL>>>(adj);
    k_final<<<(NROWS * 32) / 256, 256>>>(out);
}

// round 7
// speedup vs baseline: 1.4996x; 1.4996x over previous
#include <cuda_runtime.h>
#include <cuda_bf16.h>
#include <cstdint>
#include <cstddef>

#define NROWS 8192
#define FD 64
#define CJ 128
#define TILE_I 128
#define JSPLIT 8
#define NCHUNKS 64
#define BIMG 36864            // per-chunk B image: 144 rows x 256 B (U;V)

typedef unsigned long long ull;

__device__ float g_Wh[NROWS * FD];
__device__ float g_s[NROWS], g_d[NROWS];
__device__ float g_es[NROWS], g_fs[NROWS], g_ed[NROWS], g_fd[NROWS];
__device__ uint8_t g_UV[NCHUNKS * BIMG];          // prepacked swizzled B images
__device__ float g_pacc[JSPLIT][NROWS][FD];
__device__ float g_pl[JSPLIT][NROWS];

__device__ __forceinline__ float fast_exp(float t) {
    float x = t * 1.4426950408889634f;
    x = fminf(fmaxf(x, -126.0f), 126.0f);
    float c = x + 12582912.0f;
    int   ic = __float_as_int(c);
    float f  = x - (c - 12582912.0f);
    float y  = f * 0.6931471805599453f;
    float p = 1.3888889e-3f;
    p = fmaf(p, y, 8.3333333e-3f);
    p = fmaf(p, y, 4.1666667e-2f);
    p = fmaf(p, y, 1.6666667e-1f);
    p = fmaf(p, y, 0.5f);
    p = fmaf(p, y, 1.0f);
    p = fmaf(p, y, 1.0f);
    return p * __int_as_float(((ic & 0x7FFFFF) - 0x400000 + 127) << 23);
}

__device__ __forceinline__ uint32_t smem_u32(const void* p) {
    uint32_t a;
    asm("{ .reg .u64 t; cvta.to.shared.u64 t, %1; cvt.u32.u64 %0, t; }"
        : "=r"(a) : "l"(p));
    return a;
}
#define LDSM4(a0, a1, a2, a3, ad)                                              \
    asm volatile("ldmatrix.sync.aligned.m8n8.x4.shared.b16 {%0,%1,%2,%3}, [%4];" \
                 : "=r"(a0), "=r"(a1), "=r"(a2), "=r"(a3) : "r"(ad))
#define LDSM2(b0, b1, ad)                                                      \
    asm volatile("ldmatrix.sync.aligned.m8n8.x2.shared.b16 {%0,%1}, [%2];"     \
                 : "=r"(b0), "=r"(b1) : "r"(ad))
#define MMA16816(d, a0, a1, a2, a3, b0, b1)                                    \
    asm volatile("mma.sync.aligned.m16n8k16.row.col.f32.bf16.bf16.f32 "        \
                 "{%0,%1,%2,%3}, {%4,%5,%6,%7}, {%8,%9}, {%0,%1,%2,%3};"       \
                 : "+f"((d)[0]), "+f"((d)[1]), "+f"((d)[2]), "+f"((d)[3])      \
                 : "r"(a0), "r"(a1), "r"(a2), "r"(a3), "r"(b0), "r"(b1))

// ---------------------------------------------------------------------------
// K1: Wh = X@W, fused s/d and exp-factor tables
// ---------------------------------------------------------------------------
__global__ __launch_bounds__(128) void k_wh(const float* __restrict__ inp,
                                            const float* __restrict__ W,
                                            const float* __restrict__ a) {
    __shared__ float sIn[16 * 65];
    __shared__ float sW[64 * 64];
    __shared__ float sA[128];
    int tid = threadIdx.x;
    int i0  = blockIdx.x * 16;
    for (int idx = tid; idx < 1024; idx += 128) {
        int r = idx >> 6, k = idx & 63;
        sIn[r * 65 + k] = inp[i0 * 64 + idx];
    }
    const float4* W4 = (const float4*)W;
    float4* sW4w = (float4*)sW;
#pragma unroll
    for (int q = 0; q < 8; ++q) sW4w[tid + q * 128] = W4[tid + q * 128];
    if (tid < 128) sA[tid] = a[tid];
    __syncthreads();

    int r = tid >> 3, fg = tid & 7;
    float acc[8];
#pragma unroll
    for (int q = 0; q < 8; ++q) acc[q] = 0.f;
    const float4* sW4 = (const float4*)sW;
#pragma unroll 8
    for (int k = 0; k < 64; ++k) {
        float x = sIn[r * 65 + k];
        float4 w0 = sW4[k * 16 + fg * 2 + 0];
        float4 w1 = sW4[k * 16 + fg * 2 + 1];
        acc[0] = fmaf(x, w0.x, acc[0]); acc[1] = fmaf(x, w0.y, acc[1]);
        acc[2] = fmaf(x, w0.z, acc[2]); acc[3] = fmaf(x, w0.w, acc[3]);
        acc[4] = fmaf(x, w1.x, acc[4]); acc[5] = fmaf(x, w1.y, acc[5]);
        acc[6] = fmaf(x, w1.z, acc[6]); acc[7] = fmaf(x, w1.w, acc[7]);
    }
    int row = i0 + r;
    float ps = 0.f, pd = 0.f;
#pragma unroll
    for (int q = 0; q < 8; ++q) {
        ps = fmaf(acc[q], sA[fg * 8 + q], ps);
        pd = fmaf(acc[q], sA[64 + fg * 8 + q], pd);
    }
    float4* whp = (float4*)(g_Wh + row * 64 + fg * 8);
    whp[0] = make_float4(acc[0], acc[1], acc[2], acc[3]);
    whp[1] = make_float4(acc[4], acc[5], acc[6], acc[7]);
#pragma unroll
    for (int o = 1; o < 8; o <<= 1) {
        ps += __shfl_xor_sync(0xffffffffu, ps, o, 8);
        pd += __shfl_xor_sync(0xffffffffu, pd, o, 8);
    }
    if (fg == 0) {
        float sc = fminf(fmaxf(ps, -87.f), 80.f);
        float dc = fminf(fmaxf(pd, -87.f), 80.f);
        g_s[row] = ps; g_d[row] = pd;
        g_es[row] = fast_exp(sc);        g_fs[row] = fast_exp(0.2f * sc);
        g_ed[row] = fast_exp(dc);        g_fd[row] = fast_exp(0.2f * dc);
    }
}

// ---------------------------------------------------------------------------
// K2: build pre-swizzled bf16 B images per chunk.
// Image rows 0-71:  U[n][j] = Ed_j * Wh[j][n]  (row 64 = Ed_j, 65-71 = 0)
// Image rows 72-143: V[n][j] = Fd_j * Wh[j][n] (row 136 = Fd_j)
// Row pitch 256B (128 bf16); 16B units XOR-swizzled by (row & 7).
// ---------------------------------------------------------------------------
__device__ __forceinline__ uint32_t pk_bf2(float lo, float hi) {
    uint32_t l = (uint32_t)__bfloat16_as_ushort(__float2bfloat16_rn(lo));
    uint32_t h = (uint32_t)__bfloat16_as_ushort(__float2bfloat16_rn(hi));
    return l | (h << 16);
}
__global__ __launch_bounds__(256) void k_prep() {
    int c  = blockIdx.x;
    int jb = c * CJ;
    uint8_t* base = g_UV + (size_t)c * BIMG;
    for (int idx = threadIdx.x; idx < 72 * 64; idx += 256) {
        int n = idx >> 6, jp = idx & 63, j = 2 * jp;
        float e0 = g_ed[jb + j], e1 = g_ed[jb + j + 1];
        float f0 = g_fd[jb + j], f1 = g_fd[jb + j + 1];
        float u0, u1, v0, v1;
        if (n < 64) {
            float w0 = g_Wh[(size_t)(jb + j) * 64 + n];
            float w1 = g_Wh[(size_t)(jb + j + 1) * 64 + n];
            u0 = e0 * w0; u1 = e1 * w1; v0 = f0 * w0; v1 = f1 * w1;
        } else if (n == 64) { u0 = e0; u1 = e1; v0 = f0; v1 = f1; }
        else { u0 = u1 = v0 = v1 = 0.f; }
        uint32_t c16 = (uint32_t)(jp >> 2);
        uint32_t sw  = ((c16 ^ (uint32_t)(n & 7)) << 4) + (jp & 3) * 4;
        *(uint32_t*)(base + n * 256 + sw)         = pk_bf2(u0, u1);
        *(uint32_t*)(base + (72 + n) * 256 + sw)  = pk_bf2(v0, v1);
    }
}

// ---------------------------------------------------------------------------
// K3: exact binary masks + warp-level bf16 HMMA (mma.sync.m16n8k16).
// A tile: 128 rows x 512B: units 0-15 = C (128 bf16), units 16-31 = D.
// B tile: copied prepacked image (144 x 256B).
// ---------------------------------------------------------------------------
#define SM_S   0
#define SM_ES  512
#define SM_FS  1024
#define SM_A   2048
#define SM_B   (SM_A + 128 * 512)        // 67584
#define SM_TOT (SM_B + BIMG)             // 104448

__global__ __launch_bounds__(256, 2) void k_attn(const int* __restrict__ adj) {
    extern __shared__ char smem[];
    float* sS  = (float*)(smem + SM_S);
    float* sES = (float*)(smem + SM_ES);
    float* sFS = (float*)(smem + SM_FS);
    int tid = threadIdx.x, wid = tid >> 5, lane = tid & 31;
    int itile = blockIdx.x & 63, sp = blockIdx.x >> 6;
    int i0 = itile * TILE_I;
    int rb = wid * 16;

    if (tid < 128) {
        sS[tid]  = g_s[i0 + tid];
        sES[tid] = g_es[i0 + tid];
        sFS[tid] = g_fs[i0 + tid];
    }

    float accP[36], accQ[36];
#pragma unroll
    for (int q = 0; q < 36; ++q) { accP[q] = 0.f; accQ[q] = 0.f; }

    uint32_t sAu = smem_u32(smem) + SM_A;
    uint32_t sBu = smem_u32(smem) + SM_B;
    // ldmatrix A: lane -> (row, 16B col-half)
    uint32_t aRow  = (uint32_t)rb + (lane & 15);
    uint32_t aRho  = aRow & 7;
    uint32_t aBase = sAu + aRow * 512;
    uint32_t aHalf = (uint32_t)(lane >> 4);
    // ldmatrix B: lane -> (n-row within tile, k half)
    uint32_t bRowL = (uint32_t)(lane & 7);
    uint32_t bHalf = (uint32_t)((lane >> 3) & 1);
    uint32_t bBase = sBu + bRowL * 256;

    int j0 = 4 * lane;

    for (int cc = 0; cc < 8; ++cc) {
        int gch = sp * 8 + cc;
        int jb  = gch * CJ;
        __syncthreads();
        {   // copy prepacked B image (36864 B = 2304 uint4)
            const uint4* src = (const uint4*)(g_UV + (size_t)gch * BIMG);
            uint4* dst = (uint4*)(smem + SM_B);
#pragma unroll
            for (int q = 0; q < 9; ++q) dst[tid + q * 256] = src[tid + q * 256];
        }
        // mask build: 16 rows per warp, 4 j per lane
        float4 dv = *(const float4*)(g_d + jb + j0);
        const int4* ap = (const int4*)(adj + (size_t)(i0 + rb) * NROWS + jb) + lane;
#pragma unroll
        for (int g = 0; g < 4; ++g) {
            int4 a4[4];
#pragma unroll
            for (int r = 0; r < 4; ++r)
                a4[r] = __ldg(ap + (size_t)(g * 4 + r) * (NROWS / 4));
#pragma unroll
            for (int r = 0; r < 4; ++r) {
                uint32_t R  = (uint32_t)rb + g * 4 + r;
                float    sr = sS[R];
                float t0 = sr + dv.x, t1 = sr + dv.y;
                float t2 = sr + dv.z, t3 = sr + dv.w;
                uint32_t h01 = (t0 > 0.f ? 0x3F80u : 0u) | (t1 > 0.f ? 0x3F800000u : 0u);
                uint32_t h23 = (t2 > 0.f ? 0x3F80u : 0u) | (t3 > 0.f ? 0x3F800000u : 0u);
                uint32_t m01 = (uint32_t)a4[r].x * 0xFFFFu + (uint32_t)a4[r].y * 0xFFFF0000u;
                uint32_t m23 = (uint32_t)a4[r].z * 0xFFFFu + (uint32_t)a4[r].w * 0xFFFF0000u;
                uint32_t off = R * 512 + ((((uint32_t)(lane >> 1)) ^ (R & 7)) << 4)
                             + (uint32_t)(lane & 1) * 8;
                *(uint2*)(smem + SM_A + off) = make_uint2(h01 & m01, h23 & m23);
                *(uint2*)(smem + SM_A + off + 256) =
                    make_uint2((h01 ^ 0x3F803F80u) & m01, (h23 ^ 0x3F803F80u) & m23);
            }
        }
        __syncthreads();

        // HMMA: part 0 = C@U -> accP, part 1 = D@V -> accQ
#pragma unroll
        for (int part = 0; part < 2; ++part) {
            float* acc = part ? accQ : accP;
            uint32_t bP = bBase + (uint32_t)part * 72 * 256;
#pragma unroll
            for (int ks = 0; ks < 8; ++ks) {
                uint32_t c16 = (uint32_t)part * 16 + 2 * ks + aHalf;
                uint32_t aAddr = aBase + ((c16 ^ aRho) << 4);
                uint32_t A0, A1, A2, A3;
                LDSM4(A0, A1, A2, A3, aAddr);
                uint32_t bc16 = 2 * ks + bHalf;
                uint32_t bA0 = bP + ((bc16 ^ bRowL) << 4);
#pragma unroll
                for (int nt = 0; nt < 9; ++nt) {
                    uint32_t B0, B1;
                    LDSM2(B0, B1, bA0 + (uint32_t)nt * 2048);
                    MMA16816(acc + nt * 4, A0, A1, A2, A3, B0, B1);
                }
            }
        }
    }

    // epilogue: combine Es*P + Fs*Q, write split partials
    int r1 = rb + (lane >> 2);
    int r2 = r1 + 8;
    int c0 = 2 * (lane & 3);
    float es1 = sES[r1], fs1 = sFS[r1];
    float es2 = sES[r2], fs2 = sFS[r2];
#pragma unroll
    for (int nt = 0; nt < 8; ++nt) {
        int col = nt * 8 + c0;
        float2 v1, v2;
        v1.x = es1 * accP[nt * 4 + 0] + fs1 * accQ[nt * 4 + 0];
        v1.y = es1 * accP[nt * 4 + 1] + fs1 * accQ[nt * 4 + 1];
        v2.x = es2 * accP[nt * 4 + 2] + fs2 * accQ[nt * 4 + 2];
        v2.y = es2 * accP[nt * 4 + 3] + fs2 * accQ[nt * 4 + 3];
        *(float2*)(&g_pacc[sp][i0 + r1][col]) = v1;
        *(float2*)(&g_pacc[sp][i0 + r2][col]) = v2;
    }
    if ((lane & 3) == 0) {   // sum column n=64 lives in ntile 8, c0==0
        g_pl[sp][i0 + r1] = es1 * accP[32] + fs1 * accQ[32];
        g_pl[sp][i0 + r2] = es2 * accP[34] + fs2 * accQ[34];
    }
}

// ---------------------------------------------------------------------------
// K4: combine splits, normalize, ELU
// ---------------------------------------------------------------------------
__global__ __launch_bounds__(256) void k_final(float* __restrict__ out) {
    int idx = blockIdx.x * 256 + threadIdx.x;
    int i = idx >> 5, l = idx & 31;
    float a0 = 0.f, a1 = 0.f, ls = 0.f;
#pragma unroll
    for (int sp = 0; sp < JSPLIT; ++sp) {
        float2 p = *(const float2*)(&g_pacc[sp][i][2 * l]);
        a0 += p.x; a1 += p.y;
        ls += g_pl[sp][i];
    }
    float inv = 1.0f / ls;
    a0 *= inv; a1 *= inv;
    a0 = (a0 > 0.f) ? a0 : (fast_exp(a0) - 1.f);
    a1 = (a1 > 0.f) ? a1 : (fast_exp(a1) - 1.f);
    *(float2*)(out + i * 64 + 2 * l) = make_float2(a0, a1);
}

extern "C" void kernel_launch(void* const* d_in, const int* in_sizes, int n_in,
                              void* d_out, int out_size) {
    const float* inp = (const float*)d_in[0];
    const int*   adj = (const int*)d_in[1];
    const float* W   = (const float*)d_in[2];
    const float* a   = (const float*)d_in[3];
    float*       out = (float*)d_out;

    cudaFuncSetAttribute(k_attn, cudaFuncAttributeMaxDynamicSharedMemorySize,
                         SM_TOT);

    k_wh<<<NROWS / 16, 128>>>(inp, W, a);
    k_prep<<<NCHUNKS, 256>>>();
    k_attn<<<64 * JSPLIT, 256, SM_TOT>>>(adj);
    k_final<<<(NROWS * 32) / 256, 256>>>(out);
}

// round 8
// speedup vs baseline: 2.0427x; 1.3622x over previous
#include <cuda_runtime.h>
#include <cuda_bf16.h>
#include <cstdint>
#include <cstddef>

#define NROWS 8192
#define FD 64
#define CJ 128
#define TILE_I 128
#define JSPLIT 8
#define NCHUNKS 64
#define BIMG 36864            // per-chunk B image: 144 rows x 256 B (U;V)

typedef unsigned long long ull;

__device__ float g_Wh[NROWS * FD];
__device__ float g_s[NROWS], g_d[NROWS];
__device__ float g_es[NROWS], g_fs[NROWS], g_ed[NROWS], g_fd[NROWS];
__device__ uint8_t g_UV[NCHUNKS * BIMG];          // prepacked swizzled B images
__device__ float g_pacc[JSPLIT][NROWS][FD];
__device__ float g_pl[JSPLIT][NROWS];

__device__ __forceinline__ float fast_exp(float t) {
    float x = t * 1.4426950408889634f;
    x = fminf(fmaxf(x, -126.0f), 126.0f);
    float c = x + 12582912.0f;
    int   ic = __float_as_int(c);
    float f  = x - (c - 12582912.0f);
    float y  = f * 0.6931471805599453f;
    float p = 1.3888889e-3f;
    p = fmaf(p, y, 8.3333333e-3f);
    p = fmaf(p, y, 4.1666667e-2f);
    p = fmaf(p, y, 1.6666667e-1f);
    p = fmaf(p, y, 0.5f);
    p = fmaf(p, y, 1.0f);
    p = fmaf(p, y, 1.0f);
    return p * __int_as_float(((ic & 0x7FFFFF) - 0x400000 + 127) << 23);
}

__device__ __forceinline__ uint32_t smem_u32(const void* p) {
    uint32_t a;
    asm("{ .reg .u64 t; cvta.to.shared.u64 t, %1; cvt.u32.u64 %0, t; }"
        : "=r"(a) : "l"(p));
    return a;
}
#define LDSM4(a0, a1, a2, a3, ad)                                              \
    asm volatile("ldmatrix.sync.aligned.m8n8.x4.shared.b16 {%0,%1,%2,%3}, [%4];" \
                 : "=r"(a0), "=r"(a1), "=r"(a2), "=r"(a3) : "r"(ad))
#define LDSM2(b0, b1, ad)                                                      \
    asm volatile("ldmatrix.sync.aligned.m8n8.x2.shared.b16 {%0,%1}, [%2];"     \
                 : "=r"(b0), "=r"(b1) : "r"(ad))
#define MMA16816(d, a0, a1, a2, a3, b0, b1)                                    \
    asm volatile("mma.sync.aligned.m16n8k16.row.col.f32.bf16.bf16.f32 "        \
                 "{%0,%1,%2,%3}, {%4,%5,%6,%7}, {%8,%9}, {%0,%1,%2,%3};"       \
                 : "+f"((d)[0]), "+f"((d)[1]), "+f"((d)[2]), "+f"((d)[3])      \
                 : "r"(a0), "r"(a1), "r"(a2), "r"(a3), "r"(b0), "r"(b1))

// ---------------------------------------------------------------------------
// K1: Wh = X@W, fused s/d and exp-factor tables.
// grid=1024: 8 rows/block, 128 thr: thread (r = tid>>4, fg = tid&15) -> 4 feats.
// ---------------------------------------------------------------------------
__global__ __launch_bounds__(128) void k_wh(const float* __restrict__ inp,
                                            const float* __restrict__ W,
                                            const float* __restrict__ a) {
    __shared__ float sIn[8 * 65];
    __shared__ float sW[64 * 64];
    __shared__ float sA[128];
    int tid = threadIdx.x;
    int i0  = blockIdx.x * 8;
    for (int idx = tid; idx < 512; idx += 128) {
        int r = idx >> 6, k = idx & 63;
        sIn[r * 65 + k] = inp[i0 * 64 + idx];
    }
    const float4* W4 = (const float4*)W;
    float4* sW4w = (float4*)sW;
#pragma unroll
    for (int q = 0; q < 8; ++q) sW4w[tid + q * 128] = W4[tid + q * 128];
    if (tid < 128) sA[tid] = a[tid];
    __syncthreads();

    int r = tid >> 4, fg = tid & 15;
    float acc[4];
#pragma unroll
    for (int q = 0; q < 4; ++q) acc[q] = 0.f;
    const float4* sW4 = (const float4*)sW;
#pragma unroll 16
    for (int k = 0; k < 64; ++k) {
        float  x = sIn[r * 65 + k];
        float4 w = sW4[k * 16 + fg];
        acc[0] = fmaf(x, w.x, acc[0]);
        acc[1] = fmaf(x, w.y, acc[1]);
        acc[2] = fmaf(x, w.z, acc[2]);
        acc[3] = fmaf(x, w.w, acc[3]);
    }
    int row = i0 + r;
    float ps = 0.f, pd = 0.f;
#pragma unroll
    for (int q = 0; q < 4; ++q) {
        ps = fmaf(acc[q], sA[fg * 4 + q], ps);
        pd = fmaf(acc[q], sA[64 + fg * 4 + q], pd);
    }
    *(float4*)(g_Wh + row * 64 + fg * 4) =
        make_float4(acc[0], acc[1], acc[2], acc[3]);
#pragma unroll
    for (int o = 1; o < 16; o <<= 1) {
        ps += __shfl_xor_sync(0xffffffffu, ps, o, 16);
        pd += __shfl_xor_sync(0xffffffffu, pd, o, 16);
    }
    if (fg == 0) {
        float sc = fminf(fmaxf(ps, -87.f), 80.f);
        float dc = fminf(fmaxf(pd, -87.f), 80.f);
        g_s[row] = ps; g_d[row] = pd;
        g_es[row] = fast_exp(sc);        g_fs[row] = fast_exp(0.2f * sc);
        g_ed[row] = fast_exp(dc);        g_fd[row] = fast_exp(0.2f * dc);
    }
}

// ---------------------------------------------------------------------------
// K2: build pre-swizzled bf16 B images per chunk (unchanged from R7).
// ---------------------------------------------------------------------------
__device__ __forceinline__ uint32_t pk_bf2(float lo, float hi) {
    uint32_t l = (uint32_t)__bfloat16_as_ushort(__float2bfloat16_rn(lo));
    uint32_t h = (uint32_t)__bfloat16_as_ushort(__float2bfloat16_rn(hi));
    return l | (h << 16);
}
__global__ __launch_bounds__(256) void k_prep() {
    int c  = blockIdx.x;
    int jb = c * CJ;
    uint8_t* base = g_UV + (size_t)c * BIMG;
    for (int idx = threadIdx.x; idx < 72 * 64; idx += 256) {
        int n = idx >> 6, jp = idx & 63, j = 2 * jp;
        float e0 = g_ed[jb + j], e1 = g_ed[jb + j + 1];
        float f0 = g_fd[jb + j], f1 = g_fd[jb + j + 1];
        float u0, u1, v0, v1;
        if (n < 64) {
            float w0 = g_Wh[(size_t)(jb + j) * 64 + n];
            float w1 = g_Wh[(size_t)(jb + j + 1) * 64 + n];
            u0 = e0 * w0; u1 = e1 * w1; v0 = f0 * w0; v1 = f1 * w1;
        } else if (n == 64) { u0 = e0; u1 = e1; v0 = f0; v1 = f1; }
        else { u0 = u1 = v0 = v1 = 0.f; }
        uint32_t c16 = (uint32_t)(jp >> 2);
        uint32_t sw  = ((c16 ^ (uint32_t)(n & 7)) << 4) + (jp & 3) * 4;
        *(uint32_t*)(base + n * 256 + sw)         = pk_bf2(u0, u1);
        *(uint32_t*)(base + (72 + n) * 256 + sw)  = pk_bf2(v0, v1);
    }
}

// ---------------------------------------------------------------------------
// K3: exact binary masks + HMMA. Warp split: part (C/D) x 32-row group, so
// each B fragment is read by 4 warps instead of 8 (halves smem B traffic).
// Epilogue stages P/Q through smem once and combines Es*P + Fs*Q.
// ---------------------------------------------------------------------------
#define SM_S   0
#define SM_ES  512
#define SM_FS  1024
#define SM_A   2048
#define SM_B   (SM_A + 128 * 512)        // 67584
#define SM_TOT (SM_B + BIMG)             // 104448
#define CPITCH 76                        // combine-stage row pitch (floats)

__global__ __launch_bounds__(256, 2) void k_attn(const int* __restrict__ adj) {
    extern __shared__ char smem[];
    float* sS  = (float*)(smem + SM_S);
    float* sES = (float*)(smem + SM_ES);
    float* sFS = (float*)(smem + SM_FS);
    int tid = threadIdx.x, wid = tid >> 5, lane = tid & 31;
    int itile = blockIdx.x & 63, sp = blockIdx.x >> 6;
    int i0 = itile * TILE_I;
    int rb = wid * 16;                 // build rows (all warps build C and D)

    if (tid < 128) {
        sS[tid]  = g_s[i0 + tid];
        sES[tid] = g_es[i0 + tid];
        sFS[tid] = g_fs[i0 + tid];
    }

    // MMA ownership: part = wid>>2 (0:C@U, 1:D@V), rows mrb..mrb+31
    int part = wid >> 2;
    int mrb  = (wid & 3) * 32;

    float acc[72];                     // [nt][rowhalf][4]
#pragma unroll
    for (int q = 0; q < 72; ++q) acc[q] = 0.f;

    uint32_t sAu = smem_u32(smem) + SM_A;
    uint32_t sBu = smem_u32(smem) + SM_B;
    uint32_t aRow0 = (uint32_t)mrb + (lane & 15);
    uint32_t aRow1 = aRow0 + 16;
    uint32_t aB0 = sAu + aRow0 * 512;
    uint32_t aB1 = sAu + aRow1 * 512;
    uint32_t cBase = (uint32_t)part * 16 + (uint32_t)(lane >> 4);
    uint32_t bRowL = (uint32_t)(lane & 7);
    uint32_t bHalf = (uint32_t)((lane >> 3) & 1);
    uint32_t bBase = sBu + bRowL * 256 + (uint32_t)part * 72 * 256;

    int j0 = 4 * lane;

    for (int cc = 0; cc < 8; ++cc) {
        int gch = sp * 8 + cc;
        int jb  = gch * CJ;
        __syncthreads();
        {   // copy prepacked B image (36864 B = 2304 uint4)
            const uint4* src = (const uint4*)(g_UV + (size_t)gch * BIMG);
            uint4* dst = (uint4*)(smem + SM_B);
#pragma unroll
            for (int q = 0; q < 9; ++q) dst[tid + q * 256] = src[tid + q * 256];
        }
        // mask build: 16 rows per warp, 4 j per lane (unchanged from R7)
        float4 dv = *(const float4*)(g_d + jb + j0);
        const int4* ap = (const int4*)(adj + (size_t)(i0 + rb) * NROWS + jb) + lane;
#pragma unroll
        for (int g = 0; g < 4; ++g) {
            int4 a4[4];
#pragma unroll
            for (int r = 0; r < 4; ++r)
                a4[r] = __ldg(ap + (size_t)(g * 4 + r) * (NROWS / 4));
#pragma unroll
            for (int r = 0; r < 4; ++r) {
                uint32_t R  = (uint32_t)rb + g * 4 + r;
                float    sr = sS[R];
                float t0 = sr + dv.x, t1 = sr + dv.y;
                float t2 = sr + dv.z, t3 = sr + dv.w;
                uint32_t h01 = (t0 > 0.f ? 0x3F80u : 0u) | (t1 > 0.f ? 0x3F800000u : 0u);
                uint32_t h23 = (t2 > 0.f ? 0x3F80u : 0u) | (t3 > 0.f ? 0x3F800000u : 0u);
                uint32_t m01 = (uint32_t)a4[r].x * 0xFFFFu + (uint32_t)a4[r].y * 0xFFFF0000u;
                uint32_t m23 = (uint32_t)a4[r].z * 0xFFFFu + (uint32_t)a4[r].w * 0xFFFF0000u;
                uint32_t off = R * 512 + ((((uint32_t)(lane >> 1)) ^ (R & 7)) << 4)
                             + (uint32_t)(lane & 1) * 8;
                *(uint2*)(smem + SM_A + off) = make_uint2(h01 & m01, h23 & m23);
                *(uint2*)(smem + SM_A + off + 256) =
                    make_uint2((h01 ^ 0x3F803F80u) & m01, (h23 ^ 0x3F803F80u) & m23);
            }
        }
        __syncthreads();

        // HMMA: this warp's part only, 32 rows, all 9 n-tiles
#pragma unroll
        for (int ks = 0; ks < 8; ++ks) {
            uint32_t c16 = cBase + 2 * (uint32_t)ks;
            uint32_t A0, A1, A2, A3, A4, A5, A6, A7;
            LDSM4(A0, A1, A2, A3, aB0 + ((c16 ^ (aRow0 & 7)) << 4));
            LDSM4(A4, A5, A6, A7, aB1 + ((c16 ^ (aRow1 & 7)) << 4));
            uint32_t bc16 = 2 * (uint32_t)ks + bHalf;
            uint32_t bA0  = bBase + ((bc16 ^ bRowL) << 4);
#pragma unroll
            for (int nt = 0; nt < 9; ++nt) {
                uint32_t B0, B1;
                LDSM2(B0, B1, bA0 + (uint32_t)nt * 2048);
                MMA16816(acc + nt * 8,     A0, A1, A2, A3, B0, B1);
                MMA16816(acc + nt * 8 + 4, A4, A5, A6, A7, B0, B1);
            }
        }
    }

    // ---- epilogue: stage P/Q to smem, combine Es*P + Fs*Q ----
    __syncthreads();                   // A/B tiles dead; reuse as staging
    float* sC = (float*)(smem + SM_A); // [2][128][CPITCH]
    {
        float* base = sC + (size_t)part * 128 * CPITCH + mrb * CPITCH;
#pragma unroll
        for (int rh = 0; rh < 2; ++rh) {
            int r1 = rh * 16 + (lane >> 2);
            int r2 = r1 + 8;
#pragma unroll
            for (int nt = 0; nt < 9; ++nt) {
                int col = nt * 8 + 2 * (lane & 3);
                *(float2*)(base + r1 * CPITCH + col) =
                    make_float2(acc[nt * 8 + rh * 4 + 0], acc[nt * 8 + rh * 4 + 1]);
                *(float2*)(base + r2 * CPITCH + col) =
                    make_float2(acc[nt * 8 + rh * 4 + 2], acc[nt * 8 + rh * 4 + 3]);
            }
        }
    }
    __syncthreads();
    {
        int row  = tid >> 1, half = tid & 1;
        float es = sES[row], fs = sFS[row];
        const float* pR = sC + row * CPITCH;
        const float* qR = sC + 128 * CPITCH + row * CPITCH;
        float4* o4 = (float4*)(&g_pacc[sp][i0 + row][half * 32]);
#pragma unroll
        for (int n = 0; n < 32; n += 4) {
            int nn = half * 32 + n;
            float4 v;
            v.x = es * pR[nn + 0] + fs * qR[nn + 0];
            v.y = es * pR[nn + 1] + fs * qR[nn + 1];
            v.z = es * pR[nn + 2] + fs * qR[nn + 2];
            v.w = es * pR[nn + 3] + fs * qR[nn + 3];
            o4[n >> 2] = v;
        }
        if (half == 0)
            g_pl[sp][i0 + row] = es * pR[64] + fs * qR[64];
    }
}

// ---------------------------------------------------------------------------
// K4: combine splits, normalize, ELU
// ---------------------------------------------------------------------------
__global__ __launch_bounds__(256) void k_final(float* __restrict__ out) {
    int idx = blockIdx.x * 256 + threadIdx.x;
    int i = idx >> 5, l = idx & 31;
    float a0 = 0.f, a1 = 0.f, ls = 0.f;
#pragma unroll
    for (int sp = 0; sp < JSPLIT; ++sp) {
        float2 p = *(const float2*)(&g_pacc[sp][i][2 * l]);
        a0 += p.x; a1 += p.y;
        ls += g_pl[sp][i];
    }
    float inv = 1.0f / ls;
    a0 *= inv; a1 *= inv;
    a0 = (a0 > 0.f) ? a0 : (fast_exp(a0) - 1.f);
    a1 = (a1 > 0.f) ? a1 : (fast_exp(a1) - 1.f);
    *(float2*)(out + i * 64 + 2 * l) = make_float2(a0, a1);
}

extern "C" void kernel_launch(void* const* d_in, const int* in_sizes, int n_in,
                              void* d_out, int out_size) {
    const float* inp = (const float*)d_in[0];
    const int*   adj = (const int*)d_in[1];
    const float* W   = (const float*)d_in[2];
    const float* a   = (const float*)d_in[3];
    float*       out = (float*)d_out;

    cudaFuncSetAttribute(k_attn, cudaFuncAttributeMaxDynamicSharedMemorySize,
                         SM_TOT);

    k_wh<<<NROWS / 8, 128>>>(inp, W, a);
    k_prep<<<NCHUNKS, 256>>>();
    k_attn<<<64 * JSPLIT, 256, SM_TOT>>>(adj);
    k_final<<<(NROWS * 32) / 256, 256>>>(out);
}